// round 3
// baseline (speedup 1.0000x reference)
#include <cuda_runtime.h>
#include <math.h>

// ---------------------------------------------------------------------------
// CrossWaveletTransform: real part of pywt cwt(x, scales=1..128, 'cmor')
//
// out[b,s,t] = sum_{k=0}^{16s+1} x[b, t-8s+k] * W[s,k]
//   W[s,k] = -sqrt(s) * (filt[s,k-1] - filt[s,k])
//   filt[s,k] = f32(int_psi[ floor(k / (s*step)) ]),  k in [0, 16s], else 0
// ---------------------------------------------------------------------------

#define L_IN     8192
#define N_B      32
#define N_S      128
#define KMAXPAD  2052              // ceil((16*128+2)/18)*18
#define THREADS  256
#define R_OUT    16
#define T_TILE   (THREADS * R_OUT) // 4096 outputs per CTA
#define XS_PHYS  6928              // phys(6149)=6917 -> padded

__device__ float g_ip[1024];            // int_psi, f32
__device__ float g_W[N_S * KMAXPAD];    // per-scale diff filters, zero padded

typedef unsigned long long ull;

// --- pure-register pack/unpack via PTX (no unions -> no SROA failures) -----

__device__ __forceinline__ ull fpack(float lo, float hi) {
    ull r;
    asm("mov.b64 %0, {%1, %2};" : "=l"(r) : "f"(lo), "f"(hi));
    return r;
}
__device__ __forceinline__ void funpack(float& lo, float& hi, ull v) {
    asm("mov.b64 {%0, %1}, %2;" : "=f"(lo), "=f"(hi) : "l"(v));
}
// (a.hi, b.lo) -- the odd-offset sliding pair
__device__ __forceinline__ ull shift_pair(ull a, ull b) {
    ull r;
    asm("{\n\t"
        ".reg .b32 al, ah, bl, bh;\n\t"
        "mov.b64 {al, ah}, %1;\n\t"
        "mov.b64 {bl, bh}, %2;\n\t"
        "mov.b64 %0, {ah, bl};\n\t"
        "}" : "=l"(r) : "l"(a), "l"(b));
    return r;
}
// packed dual FP32 FMA (Blackwell): 2x FFMA throughput vs scalar
__device__ __forceinline__ ull fma2(ull a, ull b, ull c) {
    ull d;
    asm("fma.rn.f32x2 %0, %1, %2, %3;" : "=l"(d) : "l"(a), "l"(b), "l"(c));
    return d;
}

#define XPHYS(a) ((a) + (((a) >> 4) << 1))

// ---------------------------------------------------------------------------
// Filter construction (runs every launch; deterministic, ~11us total)
// ---------------------------------------------------------------------------

__global__ void build_ip_kernel() {
    __shared__ double sm[1024];
    const int n = threadIdx.x;
    const double delta = 16.0 / 1023.0;                  // numpy linspace step
    double xn = __dadd_rn(__dmul_rn((double)n, delta), -8.0);
    if (n == 1023) xn = 8.0;                             // linspace endpoint exact
    double psi = __dmul_rn(
        __dmul_rn(0.5641895835477563, exp(-__dmul_rn(xn, xn))),
        cos(__dmul_rn(6.283185307179586, xn)));
    sm[n] = psi;
    __syncthreads();
    for (int off = 1; off < 1024; off <<= 1) {
        double add = (n >= off) ? sm[n - off] : 0.0;
        __syncthreads();
        sm[n] += add;
        __syncthreads();
    }
    const double step = __dadd_rn(__dadd_rn(delta, -8.0), 8.0);
    g_ip[n] = (float)__dmul_rn(sm[n], step);
}

__device__ __forceinline__ float filt_val(int k, int s, double den) {
    if (k < 0 || k > 16 * s) return 0.0f;
    int j = (int)floor(__ddiv_rn((double)k, den));  // bit-exact vs numpy f64
    if (j > 1023) return 0.0f;
    return g_ip[j];
}

__global__ void build_W_kernel() {
    const int si = blockIdx.x;
    const int s = si + 1;
    const double delta = 16.0 / 1023.0;
    const double step = __dadd_rn(__dadd_rn(delta, -8.0), 8.0);
    const double den = __dmul_rn((double)s, step);
    const int klen = 16 * s + 2;
    const float nsq = -sqrtf((float)s);
    for (int k = threadIdx.x; k < KMAXPAD; k += blockDim.x) {
        float wv = 0.0f;
        if (k < klen)
            wv = nsq * (filt_val(k - 1, s, den) - filt_val(k, s, den));
        g_W[si * KMAXPAD + k] = wv;
    }
}

// ---------------------------------------------------------------------------
// Main convolution: FFMA2 sliding-window, one CTA per (b, scale, 4096-tile)
// ---------------------------------------------------------------------------

__global__ __launch_bounds__(THREADS, 2) void cwt_main(
    const float* __restrict__ x, float* __restrict__ out)
{
    __shared__ __align__(16) float xs[XS_PHYS];
    __shared__ __align__(16) float ws2[2 * KMAXPAD];  // splatted (w,w) pairs

    const int b    = blockIdx.x >> 1;
    const int tile = blockIdx.x & 1;
    const int si   = 127 - blockIdx.y;   // heavy scales launch first
    const int s    = si + 1;
    const int t0   = tile * T_TILE;

    const int klen     = 16 * s + 2;
    const int klen_pad = ((klen + 17) / 18) * 18;
    const int wlen     = T_TILE + klen_pad + 2;
    const int g0       = t0 - 8 * s;     // starts = 2048 - 8s in reference

    // stage x window (zero-padded at borders), swizzled for conflict-free LDS.64
    const float* xb = x + b * L_IN;
    for (int i = threadIdx.x; i < wlen; i += THREADS) {
        int g = g0 + i;
        float v = (g >= 0 && g < L_IN) ? xb[g] : 0.0f;
        xs[XPHYS(i)] = v;
    }
    // stage filter as splatted pairs: one LDS.128 yields (w[k],w[k],w[k+1],w[k+1])
    const float* wrow = g_W + si * KMAXPAD;
    for (int k = threadIdx.x; k < klen_pad; k += THREADS) {
        float w = wrow[k];
        ws2[2 * k]     = w;
        ws2[2 * k + 1] = w;
    }
    __syncthreads();

    const int o = threadIdx.x * R_OUT;   // 16 consecutive outputs per thread

    // packed sliding window: W2[m]=(v[2m],v[2m+1]), O2[m]=(v[2m+1],v[2m+2])
    ull W2[9], O2[9], acc[8];
#pragma unroll
    for (int m = 0; m < 9; m++)
        W2[m] = *reinterpret_cast<const ull*>(xs + XPHYS(o + 2 * m));
#pragma unroll
    for (int m = 0; m < 8; m++)
        O2[m] = shift_pair(W2[m], W2[m + 1]);
    O2[8] = 0ull;
#pragma unroll
    for (int m = 0; m < 8; m++) acc[m] = 0ull;

    for (int kc = 0; kc < klen_pad; kc += 18) {
#pragma unroll
        for (int jj = 0; jj < 9; jj++) {
            const int k = kc + 2 * jj;
            // k is even -> 16B-aligned: single LDS.128 broadcast of both taps
            const ulonglong2 wv =
                *reinterpret_cast<const ulonglong2*>(ws2 + 2 * k);
            const ull we = wv.x;   // (w[k],   w[k])
            const ull wo = wv.y;   // (w[k+1], w[k+1])
#pragma unroll
            for (int m = 0; m < 8; m++)
                acc[m] = fma2(W2[(jj + m) % 9], we, acc[m]);
#pragma unroll
            for (int m = 0; m < 8; m++)
                acc[m] = fma2(O2[(jj + m) % 9], wo, acc[m]);
            // slide window by one pair: load x[o+k+18], x[o+k+19]
            const ull nw = *reinterpret_cast<const ull*>(xs + XPHYS(o + k + 18));
            O2[(jj + 8) % 9] = shift_pair(W2[(jj + 8) % 9], nw);
            W2[jj % 9] = nw;
        }
    }

    float* op = out + (((size_t)b * N_S + si) * L_IN + t0 + o);
#pragma unroll
    for (int m = 0; m < 4; m++) {
        float4 v;
        funpack(v.x, v.y, acc[2 * m]);
        funpack(v.z, v.w, acc[2 * m + 1]);
        reinterpret_cast<float4*>(op)[m] = v;
    }
}

// ---------------------------------------------------------------------------

extern "C" void kernel_launch(void* const* d_in, const int* in_sizes, int n_in,
                              void* d_out, int out_size) {
    const float* x = (const float*)d_in[0];
    float* out = (float*)d_out;

    build_ip_kernel<<<1, 1024>>>();
    build_W_kernel<<<N_S, 256>>>();

    dim3 grid(N_B * 2, N_S);
    cwt_main<<<grid, THREADS>>>(x, out);
}

// round 5
// speedup vs baseline: 1.1232x; 1.1232x over previous
#include <cuda_runtime.h>
#include <math.h>

// ---------------------------------------------------------------------------
// CrossWaveletTransform: real part of pywt cwt(x, scales=1..128, 'cmor')
//
// out[b,s,t] = sum_{k=0}^{16s+1} x[b, t-8s+k] * W[s,k]
//   W[s,k] = -sqrt(s) * (filt[s,k-1] - filt[s,k])
//   filt[s,k] = f32(int_psi[ floor(k / (s*step)) ]),  k in [0, 16s], else 0
// ---------------------------------------------------------------------------

#define L_IN     8192
#define N_B      32
#define N_S      128
#define KMAXPAD  2052              // ceil((16*128+2)/18)*18
#define THREADS  256
#define R_OUT    16
#define T_TILE   (THREADS * R_OUT) // 4096 outputs per CTA
#define XS_PHYS  6928              // phys(6149)=6917 -> padded

__device__ float g_W[N_S * KMAXPAD];    // per-scale diff filters, zero padded

typedef unsigned long long ull;

union F2U { ull u; float2 f; };

__device__ __forceinline__ ull fpack(float lo, float hi) {
    F2U t; t.f.x = lo; t.f.y = hi; return t.u;
}
__device__ __forceinline__ float ulo(ull v) { F2U t; t.u = v; return t.f.x; }
__device__ __forceinline__ float uhi(ull v) { F2U t; t.u = v; return t.f.y; }

// packed dual FP32 FMA (Blackwell sm_100a): 2x FFMA throughput vs scalar
__device__ __forceinline__ ull fma2(ull a, ull b, ull c) {
    ull d;
    asm("fma.rn.f32x2 %0, %1, %2, %3;" : "=l"(d) : "l"(a), "l"(b), "l"(c));
    return d;
}

#define XPHYS(a) ((a) + (((a) >> 4) << 1))

// ---------------------------------------------------------------------------
// Filter construction, single kernel (grid=128): each CTA redundantly
// computes int_psi (f64 scan in smem), then writes its scale's W row.
// Deterministic, ~6us. One kernel -> 2 launches/replay -> ncu -s 5 lands
// on cwt_main.
// ---------------------------------------------------------------------------

__global__ void build_filters_kernel() {
    __shared__ double sm[1024];
    __shared__ float ipf[1024];
    const int n = threadIdx.x;
    const double delta = 16.0 / 1023.0;                  // numpy linspace step
    double xn = __dadd_rn(__dmul_rn((double)n, delta), -8.0);
    if (n == 1023) xn = 8.0;                             // linspace endpoint exact
    // psi = pi^-0.5 * exp(-x^2) * cos(2*pi*x), f64, numpy op order
    double psi = __dmul_rn(
        __dmul_rn(0.5641895835477563, exp(-__dmul_rn(xn, xn))),
        cos(__dmul_rn(6.283185307179586, xn)));
    sm[n] = psi;
    __syncthreads();
    // inclusive scan (f64; association diff vs numpy cumsum ~1e-15, irrelevant)
    for (int off = 1; off < 1024; off <<= 1) {
        double add = (n >= off) ? sm[n - off] : 0.0;
        __syncthreads();
        sm[n] += add;
        __syncthreads();
    }
    const double step = __dadd_rn(__dadd_rn(delta, -8.0), 8.0);
    ipf[n] = (float)__dmul_rn(sm[n], step);   // f32 int_psi (matches reference)
    __syncthreads();

    const int si = blockIdx.x;
    const int s = si + 1;
    const double den = __dmul_rn((double)s, step);
    const int klen = 16 * s + 2;
    const float nsq = -sqrtf((float)s);
    for (int k = n; k < KMAXPAD; k += blockDim.x) {
        float wv = 0.0f;
        if (k < klen) {
            float fm1 = 0.0f, f0 = 0.0f;
            if (k - 1 >= 0 && k - 1 <= 16 * s) {
                int j = (int)floor(__ddiv_rn((double)(k - 1), den));
                if (j <= 1023) fm1 = ipf[j];
            }
            if (k <= 16 * s) {
                int j = (int)floor(__ddiv_rn((double)k, den));
                if (j <= 1023) f0 = ipf[j];
            }
            wv = nsq * (fm1 - f0);
        }
        g_W[si * KMAXPAD + k] = wv;
    }
}

// ---------------------------------------------------------------------------
// Main convolution: FFMA2 sliding-window, one CTA per (b, scale, 4096-tile)
// (identical to the round-2 version that measured 1581.8us)
// ---------------------------------------------------------------------------

__global__ __launch_bounds__(THREADS) void cwt_main(
    const float* __restrict__ x, float* __restrict__ out)
{
    __shared__ __align__(16) float xs[XS_PHYS];
    __shared__ __align__(16) float ws2[2 * KMAXPAD];  // splatted (w,w) pairs

    const int b    = blockIdx.x >> 1;
    const int tile = blockIdx.x & 1;
    const int si   = 127 - blockIdx.y;   // heavy scales launch first
    const int s    = si + 1;
    const int t0   = tile * T_TILE;

    const int klen     = 16 * s + 2;
    const int klen_pad = ((klen + 17) / 18) * 18;
    const int wlen     = T_TILE + klen_pad + 2;
    const int g0       = t0 - 8 * s;     // starts = 2048 - 8s in reference

    // stage x window (zero-padded at borders), swizzled for conflict-free LDS.64
    const float* xb = x + b * L_IN;
    for (int i = threadIdx.x; i < wlen; i += THREADS) {
        int g = g0 + i;
        float v = (g >= 0 && g < L_IN) ? xb[g] : 0.0f;
        xs[XPHYS(i)] = v;
    }
    // stage filter as splatted pairs so FMA2 b-operand is a single LDS.64
    const float* wrow = g_W + si * KMAXPAD;
    for (int k = threadIdx.x; k < klen_pad; k += THREADS) {
        float w = wrow[k];
        ws2[2 * k]     = w;
        ws2[2 * k + 1] = w;
    }
    __syncthreads();

    const int o = threadIdx.x * R_OUT;   // 16 consecutive outputs per thread

    // packed sliding window: W2[m]=(v[2m],v[2m+1]), O2[m]=(v[2m+1],v[2m+2])
    ull W2[9], O2[9], acc[8];
#pragma unroll
    for (int m = 0; m < 9; m++)
        W2[m] = *reinterpret_cast<const ull*>(xs + XPHYS(o + 2 * m));
#pragma unroll
    for (int m = 0; m < 8; m++)
        O2[m] = fpack(uhi(W2[m]), ulo(W2[m + 1]));
    O2[8] = 0ull;
#pragma unroll
    for (int m = 0; m < 8; m++) acc[m] = 0ull;

    for (int kc = 0; kc < klen_pad; kc += 18) {
#pragma unroll
        for (int jj = 0; jj < 9; jj++) {
            const int k = kc + 2 * jj;
            const ull we = *reinterpret_cast<const ull*>(ws2 + 2 * k);     // (w[k],w[k])
            const ull wo = *reinterpret_cast<const ull*>(ws2 + 2 * k + 2); // (w[k+1],w[k+1])
#pragma unroll
            for (int m = 0; m < 8; m++)
                acc[m] = fma2(W2[(jj + m) % 9], we, acc[m]);
#pragma unroll
            for (int m = 0; m < 8; m++)
                acc[m] = fma2(O2[(jj + m) % 9], wo, acc[m]);
            // slide window by one pair: load x[o+k+18], x[o+k+19]
            const ull nw = *reinterpret_cast<const ull*>(xs + XPHYS(o + k + 18));
            O2[(jj + 8) % 9] = fpack(uhi(W2[(jj + 8) % 9]), ulo(nw));
            W2[jj % 9] = nw;
        }
    }

    float* op = out + (((size_t)b * N_S + si) * L_IN + t0 + o);
#pragma unroll
    for (int m = 0; m < 4; m++) {
        float4 v;
        v.x = ulo(acc[2 * m]);
        v.y = uhi(acc[2 * m]);
        v.z = ulo(acc[2 * m + 1]);
        v.w = uhi(acc[2 * m + 1]);
        reinterpret_cast<float4*>(op)[m] = v;
    }
}

// ---------------------------------------------------------------------------

extern "C" void kernel_launch(void* const* d_in, const int* in_sizes, int n_in,
                              void* d_out, int out_size) {
    const float* x = (const float*)d_in[0];
    float* out = (float*)d_out;

    build_filters_kernel<<<N_S, 1024>>>();

    dim3 grid(N_B * 2, N_S);
    cwt_main<<<grid, THREADS>>>(x, out);
}